// round 3
// baseline (speedup 1.0000x reference)
#include <cuda_runtime.h>
#include <cstdint>

// Decoder_90486370992920
// Inputs (metadata order):
//   d_in[0] partition [N,64] f32
//   d_in[1] abs_actions [64] f32
//   d_in[2] u [N,64] f32
//   d_in[3] W [N,2,2] f32
//   d_in[4] b [N,2] f32
// Output: weights [N,2] f32 at [0,2N), actions [N,2] at [2N,4N)
//
// Math:
//   argmax_m (logit(p) + gumbel) == argmax_m r_m/s_m, r=p/(1-p), s=-log(u),
//   compared via cross-multiplication (monotone equivalent, no divisions).
//   weights = sigmoid(W @ [idx, abs_actions[idx]] + b) as 1/(1+exp(-y)) with
//   FTZ semantics (XLA compiles f32 with flush-to-zero): subnormal results
//   flush to exactly 0.  Cutoff evidence: naive-inf-only cutoff left a
//   75-mismatch band == y in (-88.72, -87.33), exactly the subnormal band.
//   actions = (w > 0).

static constexpr int M = 64;
static constexpr int LANES_PER_AGENT = 16;   // each lane handles 4 columns (one float4)
static constexpr int THREADS = 256;

__global__ __launch_bounds__(THREADS)
void decoder_kernel(const float* __restrict__ part,
                    const float* __restrict__ absa,
                    const float* __restrict__ u,
                    const float* __restrict__ W,
                    const float* __restrict__ b,
                    float* __restrict__ out,
                    int nAgents,
                    long long outSize)
{
    __shared__ float sabs[M];
    if (threadIdx.x < M) sabs[threadIdx.x] = absa[threadIdx.x];
    __syncthreads();

    const int lane    = threadIdx.x & 31;
    const int gwarp   = (int)((blockIdx.x * (unsigned)blockDim.x + threadIdx.x) >> 5);
    const int agent   = gwarp * 2 + (lane >> 4);      // 2 agents per warp
    const int sub     = lane & 15;                    // 16 lanes per agent

    // clamp so whole warp stays active for shuffles
    const int ag = agent < nAgents ? agent : (nAgents - 1);
    const size_t rowBase = (size_t)ag * M + sub * 4;

    const float4 p  = __ldg(reinterpret_cast<const float4*>(part + rowBase));
    const float4 uu = __ldg(reinterpret_cast<const float4*>(u    + rowBase));

    // per-lane best over 4 columns; key = r/s tracked as (r, s) fraction
    float rb, sb; int ib;
    {
        float r0 = __fdividef(p.x, 1.0f - p.x);
        float s0 = -__logf(uu.x);
        rb = r0; sb = s0; ib = sub * 4;

        float r1 = __fdividef(p.y, 1.0f - p.y);
        float s1 = -__logf(uu.y);
        if (r1 * sb > rb * s1) { rb = r1; sb = s1; ib = sub * 4 + 1; }

        float r2 = __fdividef(p.z, 1.0f - p.z);
        float s2 = -__logf(uu.z);
        if (r2 * sb > rb * s2) { rb = r2; sb = s2; ib = sub * 4 + 2; }

        float r3 = __fdividef(p.w, 1.0f - p.w);
        float s3 = -__logf(uu.w);
        if (r3 * sb > rb * s3) { rb = r3; sb = s3; ib = sub * 4 + 3; }
    }

    // butterfly reduce across the 16 lanes of this agent (prefer lower index on ties)
    #pragma unroll
    for (int off = 8; off > 0; off >>= 1) {
        float ro = __shfl_xor_sync(0xffffffffu, rb, off, 16);
        float so = __shfl_xor_sync(0xffffffffu, sb, off, 16);
        int   io = __shfl_xor_sync(0xffffffffu, ib, off, 16);
        float lhs = ro * sb;
        float rhs = rb * so;
        if (lhs > rhs || (lhs == rhs && io < ib)) { rb = ro; sb = so; ib = io; }
    }

    if (sub == 0 && agent < nAgents) {
        const float x0 = (float)ib;
        const float x1 = sabs[ib];

        const float4 w = __ldg(reinterpret_cast<const float4*>(W + (size_t)agent * 4));
        const float2 bb = __ldg(reinterpret_cast<const float2*>(b + (size_t)agent * 2));

        float y0 = fmaf(w.x, x0, fmaf(w.y, x1, bb.x));
        float y1 = fmaf(w.z, x0, fmaf(w.w, x1, bb.y));

        // Naive sigmoid, FTZ semantics: subnormal result flushes to exact 0
        // (matches XLA's ftz f32 lowering; exp overflow -> 1/inf = 0 too).
        float e0 = expf(-y0);
        float e1 = expf(-y1);
        float s0 = 1.0f / (1.0f + e0);
        float s1 = 1.0f / (1.0f + e1);
        if (s0 < 1.17549435e-38f) s0 = 0.0f;   // FLT_MIN flush
        if (s1 < 1.17549435e-38f) s1 = 0.0f;

        float2* o = reinterpret_cast<float2*>(out + (size_t)agent * 2);
        *o = make_float2(s0, s1);

        // actions = (weight > 0)
        if (outSize >= 4LL * nAgents) {
            float a0 = (s0 > 0.0f) ? 1.0f : 0.0f;
            float a1 = (s1 > 0.0f) ? 1.0f : 0.0f;
            float2* oa = reinterpret_cast<float2*>(out + 2LL * nAgents + (size_t)agent * 2);
            *oa = make_float2(a0, a1);
        }
    }
}

extern "C" void kernel_launch(void* const* d_in, const int* in_sizes, int n_in,
                              void* d_out, int out_size)
{
    const float* part = (const float*)d_in[0];
    const float* absa = (const float*)d_in[1];
    const float* u    = (const float*)d_in[2];
    const float* W    = (const float*)d_in[3];
    const float* b    = (const float*)d_in[4];
    float* out = (float*)d_out;

    const int nAgents = in_sizes[0] / M;   // partition is [N, 64]

    const long long totalThreads = (long long)nAgents * LANES_PER_AGENT;
    const int blocks = (int)((totalThreads + THREADS - 1) / THREADS);

    decoder_kernel<<<blocks, THREADS>>>(part, absa, u, W, b, out, nAgents,
                                        (long long)out_size);
}

// round 4
// speedup vs baseline: 1.8934x; 1.8934x over previous
#include <cuda_runtime.h>
#include <cstdint>

// Decoder_90486370992920
// Inputs: d_in[0] partition [N,64] f32, d_in[1] abs_actions [64] f32,
//         d_in[2] u [N,64] f32, d_in[3] W [N,2,2] f32, d_in[4] b [N,2] f32
// Output: weights [N,2] f32 at [0,2N), actions [N,2] at [2N,4N)
//
// argmax_m (logit(p)+gumbel) == argmax_m r/s, r=p/(1-p), s=-ln u
//   == argmin_m  m  with  m = r * rcp(LG2(u))   (m<0; -1/ln2 const folded by
//   max->min flip).  rcp refined with one Newton step to keep discrimination
//   noise at the level proven passing in R3.
// Reduction: FMIN tree (exact bit propagation) + equality recovery + ballot
//   (lowest lane & lowest slot first => reference's first-occurrence tie rule).
// weights = 1/(1+exp(-y)) with accurate expf, result flushed to 0 when
//   subnormal (XLA FTZ semantics, established R2/R3). actions = (w>0).

static constexpr int M = 64;
static constexpr int LPA = 8;            // lanes per agent
static constexpr int EPL = 8;            // elements per lane
static constexpr int THREADS = 256;
static constexpr int AGENTS_PER_BLOCK = THREADS / LPA;   // 32

__device__ __forceinline__ float key_m(float p, float uu)
{
    // r = p/(1-p)
    float q = 1.0f - p;
    float rq = __frcp_rn(q);             // MUFU.RCP (+ compiler may add fixups; see note)
    float r = p * rq;
    // d = log2(u)  (negative), t ~= 1/d with one Newton refinement
    float d = __log2f(uu);               // MUFU.LG2
    float t;
    asm("rcp.approx.f32 %0, %1;" : "=f"(t) : "f"(d));   // raw approx, no fixup code
    t = t * __fmaf_rn(-d, t, 2.0f);      // Newton: t*(2-d*t)
    return r * t;                        // m < 0 ; argmin m == argmax r/s
}

__global__ __launch_bounds__(THREADS)
void decoder_kernel(const float* __restrict__ part,
                    const float* __restrict__ absa,
                    const float* __restrict__ u,
                    const float* __restrict__ W,
                    const float* __restrict__ b,
                    float* __restrict__ out,
                    int nAgents,
                    long long outSize)
{
    __shared__ float sabs[M];
    if (threadIdx.x < M) sabs[threadIdx.x] = absa[threadIdx.x];
    __syncthreads();

    const int lane = threadIdx.x & 31;
    const int sub  = lane & (LPA - 1);          // 0..7 within agent
    const int grp  = lane >> 3;                 // agent slot within warp (0..3)
    const int gwarp = (int)((blockIdx.x * (unsigned)blockDim.x + threadIdx.x) >> 5);
    const int agent = gwarp * 4 + grp;

    const int ag = agent < nAgents ? agent : (nAgents - 1);
    const size_t rowBase = (size_t)ag * M + sub * EPL;

    const float4 p0 = __ldg(reinterpret_cast<const float4*>(part + rowBase));
    const float4 p1 = __ldg(reinterpret_cast<const float4*>(part + rowBase + 4));
    const float4 u0 = __ldg(reinterpret_cast<const float4*>(u + rowBase));
    const float4 u1 = __ldg(reinterpret_cast<const float4*>(u + rowBase + 4));

    float m0 = key_m(p0.x, u0.x);
    float m1 = key_m(p0.y, u0.y);
    float m2 = key_m(p0.z, u0.z);
    float m3 = key_m(p0.w, u0.w);
    float m4 = key_m(p1.x, u1.x);
    float m5 = key_m(p1.y, u1.y);
    float m6 = key_m(p1.z, u1.z);
    float m7 = key_m(p1.w, u1.w);

    // within-lane min (argmax of r/s)
    float a = fminf(fminf(m0, m1), fminf(m2, m3));
    float c = fminf(fminf(m4, m5), fminf(m6, m7));
    float km = fminf(a, c);

    // cross-lane min over the 8 lanes of this agent
    #pragma unroll
    for (int off = 4; off > 0; off >>= 1)
        km = fminf(km, __shfl_xor_sync(0xffffffffu, km, off, LPA));

    // index recovery: exact equality against km; lowest slot wins within lane
    const int base = sub * EPL;
    int li = 1 << 20;
    if (m7 == km) li = base + 7;
    if (m6 == km) li = base + 6;
    if (m5 == km) li = base + 5;
    if (m4 == km) li = base + 4;
    if (m3 == km) li = base + 3;
    if (m2 == km) li = base + 2;
    if (m1 == km) li = base + 1;
    if (m0 == km) li = base + 0;

    unsigned bal = __ballot_sync(0xffffffffu, li < (1 << 20));
    unsigned gmask = (bal >> (grp * LPA)) & 0xffu;    // hits within this agent's lanes
    int leader = __ffs((int)gmask) - 1;               // lowest lane -> lowest index
    int widx = __shfl_sync(0xffffffffu, li, grp * LPA + leader);

    if (sub == 0 && agent < nAgents) {
        const float x0 = (float)widx;
        const float x1 = sabs[widx];

        const float4 w  = __ldg(reinterpret_cast<const float4*>(W + (size_t)agent * 4));
        const float2 bb = __ldg(reinterpret_cast<const float2*>(b + (size_t)agent * 2));

        float y0 = fmaf(w.x, x0, fmaf(w.y, x1, bb.x));
        float y1 = fmaf(w.z, x0, fmaf(w.w, x1, bb.y));

        // naive sigmoid, accurate expf, FTZ flush of subnormal results
        float s0 = 1.0f / (1.0f + expf(-y0));
        float s1 = 1.0f / (1.0f + expf(-y1));
        if (s0 < 1.17549435e-38f) s0 = 0.0f;
        if (s1 < 1.17549435e-38f) s1 = 0.0f;

        reinterpret_cast<float2*>(out + (size_t)agent * 2)[0] = make_float2(s0, s1);

        if (outSize >= 4LL * nAgents) {
            float a0 = (s0 > 0.0f) ? 1.0f : 0.0f;
            float a1 = (s1 > 0.0f) ? 1.0f : 0.0f;
            reinterpret_cast<float2*>(out + 2LL * nAgents + (size_t)agent * 2)[0] =
                make_float2(a0, a1);
        }
    }
}

extern "C" void kernel_launch(void* const* d_in, const int* in_sizes, int n_in,
                              void* d_out, int out_size)
{
    const float* part = (const float*)d_in[0];
    const float* absa = (const float*)d_in[1];
    const float* u    = (const float*)d_in[2];
    const float* W    = (const float*)d_in[3];
    const float* b    = (const float*)d_in[4];
    float* out = (float*)d_out;

    const int nAgents = in_sizes[0] / M;
    const int blocks = (nAgents + AGENTS_PER_BLOCK - 1) / AGENTS_PER_BLOCK;

    decoder_kernel<<<blocks, THREADS>>>(part, absa, u, W, b, out, nAgents,
                                        (long long)out_size);
}

// round 6
// speedup vs baseline: 2.0608x; 1.0884x over previous
#include <cuda_runtime.h>
#include <cstdint>

// Decoder_90486370992920
// Inputs: d_in[0] partition [N,64] f32, d_in[1] abs_actions [64] f32,
//         d_in[2] u [N,64] f32, d_in[3] W [N,2,2] f32, d_in[4] b [N,2] f32
// Output: weights [N,2] f32 at [0,2N), actions [N,2] at [2N,4N)
//
// argmax_m (logit(p)+gumbel) == argmax_m r/s, r=p/(1-p), s=-ln u.
// Reciprocal key WITHOUT cancellation (R5's fma(t,d,-d)=d*(t-1) amplified
// t's fp32 quantization by 1/(1-p) -> 6e-6 noise -> 3 flips -> FAIL):
//     m' = d * q * t,  q = 1-p (exact/half-ulp), t = rcp(p) (approx+Newton),
//     d = log2(u) < 0.
// m' < 0 and m' = -(q*(-d))/p is monotone increasing in r/s, so
//     argmax r/s == argmax m'  -> plain FMAX reduction.
// Non-LG2 noise ~2-3 ulp products == R4's noise class (stable single flip,
// rel_err 6.17e-4). Index recovery: FMAX propagates exact bits -> equality
// match + ballot; lowest lane/slot first == reference first-occurrence rule.
// weights = 1/(1+exp(-y)) accurate expf, subnormal flushed to 0 (XLA FTZ,
// established R2->R3). actions = (w>0).

static constexpr int M = 64;
static constexpr int LPA = 8;            // lanes per agent
static constexpr int EPL = 8;            // elements per lane
static constexpr int THREADS = 256;
static constexpr int AGENTS_PER_BLOCK = THREADS / LPA;   // 32

__device__ __forceinline__ float key_m(float p, float uu)
{
    float q = 1.0f - p;                                 // exact for p>=0.5, <=1/2 ulp else
    float t;
    asm("rcp.approx.f32 %0, %1;" : "=f"(t) : "f"(p));   // ~1/p, no fixup code
    t = t * __fmaf_rn(-p, t, 2.0f);                     // Newton -> ~0.5 ulp
    float d = __log2f(uu);                              // MUFU.LG2, d < 0
    return (d * q) * t;                                 // m' = d*(1-p)/p < 0
}

__global__ __launch_bounds__(THREADS)
void decoder_kernel(const float* __restrict__ part,
                    const float* __restrict__ absa,
                    const float* __restrict__ u,
                    const float* __restrict__ W,
                    const float* __restrict__ b,
                    float* __restrict__ out,
                    int nAgents,
                    long long outSize)
{
    __shared__ float sabs[M];
    if (threadIdx.x < M) sabs[threadIdx.x] = absa[threadIdx.x];
    __syncthreads();

    const int lane = threadIdx.x & 31;
    const int sub  = lane & (LPA - 1);          // 0..7 within agent
    const int grp  = lane >> 3;                 // agent slot within warp (0..3)
    const int gwarp = (int)((blockIdx.x * (unsigned)blockDim.x + threadIdx.x) >> 5);
    const int agent = gwarp * 4 + grp;

    const int ag = agent < nAgents ? agent : (nAgents - 1);
    const size_t rowBase = (size_t)ag * M + sub * EPL;

    const float4 p0 = __ldg(reinterpret_cast<const float4*>(part + rowBase));
    const float4 p1 = __ldg(reinterpret_cast<const float4*>(part + rowBase + 4));
    const float4 u0 = __ldg(reinterpret_cast<const float4*>(u + rowBase));
    const float4 u1 = __ldg(reinterpret_cast<const float4*>(u + rowBase + 4));

    float m0 = key_m(p0.x, u0.x);
    float m1 = key_m(p0.y, u0.y);
    float m2 = key_m(p0.z, u0.z);
    float m3 = key_m(p0.w, u0.w);
    float m4 = key_m(p1.x, u1.x);
    float m5 = key_m(p1.y, u1.y);
    float m6 = key_m(p1.z, u1.z);
    float m7 = key_m(p1.w, u1.w);

    // within-lane max (== argmax of r/s)
    float a = fmaxf(fmaxf(m0, m1), fmaxf(m2, m3));
    float c = fmaxf(fmaxf(m4, m5), fmaxf(m6, m7));
    float km = fmaxf(a, c);

    // cross-lane max over the 8 lanes of this agent
    #pragma unroll
    for (int off = 4; off > 0; off >>= 1)
        km = fmaxf(km, __shfl_xor_sync(0xffffffffu, km, off, LPA));

    // index recovery: exact equality against km; lowest slot wins within lane
    const int base = sub * EPL;
    int li = 1 << 20;
    if (m7 == km) li = base + 7;
    if (m6 == km) li = base + 6;
    if (m5 == km) li = base + 5;
    if (m4 == km) li = base + 4;
    if (m3 == km) li = base + 3;
    if (m2 == km) li = base + 2;
    if (m1 == km) li = base + 1;
    if (m0 == km) li = base + 0;

    unsigned bal = __ballot_sync(0xffffffffu, li < (1 << 20));
    unsigned gmask = (bal >> (grp * LPA)) & 0xffu;    // hits within this agent's lanes
    int leader = __ffs((int)gmask) - 1;               // lowest lane -> lowest index
    int widx = __shfl_sync(0xffffffffu, li, grp * LPA + leader);

    if (sub == 0 && agent < nAgents) {
        const float x0 = (float)widx;
        const float x1 = sabs[widx];

        const float4 w  = __ldg(reinterpret_cast<const float4*>(W + (size_t)agent * 4));
        const float2 bb = __ldg(reinterpret_cast<const float2*>(b + (size_t)agent * 2));

        float y0 = fmaf(w.x, x0, fmaf(w.y, x1, bb.x));
        float y1 = fmaf(w.z, x0, fmaf(w.w, x1, bb.y));

        // naive sigmoid, accurate expf, FTZ flush of subnormal results
        float s0 = 1.0f / (1.0f + expf(-y0));
        float s1 = 1.0f / (1.0f + expf(-y1));
        if (s0 < 1.17549435e-38f) s0 = 0.0f;
        if (s1 < 1.17549435e-38f) s1 = 0.0f;

        reinterpret_cast<float2*>(out + (size_t)agent * 2)[0] = make_float2(s0, s1);

        if (outSize >= 4LL * nAgents) {
            float a0 = (s0 > 0.0f) ? 1.0f : 0.0f;
            float a1 = (s1 > 0.0f) ? 1.0f : 0.0f;
            reinterpret_cast<float2*>(out + 2LL * nAgents + (size_t)agent * 2)[0] =
                make_float2(a0, a1);
        }
    }
}

extern "C" void kernel_launch(void* const* d_in, const int* in_sizes, int n_in,
                              void* d_out, int out_size)
{
    const float* part = (const float*)d_in[0];
    const float* absa = (const float*)d_in[1];
    const float* u    = (const float*)d_in[2];
    const float* W    = (const float*)d_in[3];
    const float* b    = (const float*)d_in[4];
    float* out = (float*)d_out;

    const int nAgents = in_sizes[0] / M;
    const int blocks = (nAgents + AGENTS_PER_BLOCK - 1) / AGENTS_PER_BLOCK;

    decoder_kernel<<<blocks, THREADS>>>(part, absa, u, W, b, out, nAgents,
                                        (long long)out_size);
}